// round 3
// baseline (speedup 1.0000x reference)
#include <cuda_runtime.h>
#include <cuda_bf16.h>

#define V_SIZE 50257
#define E_SIZE 768
#define QK_SIZE 256
#define B_SIZE 4
#define T_SIZE 1024
#define M_ROWS (B_SIZE * T_SIZE)   // 4096
#define LN_EPS 1e-5f

// ---------------- scratch (static device memory; no allocation) ----------------
__device__ float g_x[M_ROWS * E_SIZE];    // layernormed hidden states (12 MB)
__device__ float g_q[M_ROWS * QK_SIZE];   // q projections (4 MB)
__device__ float g_k[M_ROWS * QK_SIZE];   // k projections (4 MB)

// ---------------- kernel 0: gather + layernorm ----------------
// one block per (b,t) row; 256 threads, 3 elements each (E=768)
__global__ void ln_kernel(const int* __restrict__ idx,
                          const float* __restrict__ emb,
                          const float* __restrict__ gamma,
                          const float* __restrict__ beta,
                          float* __restrict__ xout) {
    int r = blockIdx.x;
    int tok = idx[r];
    const float* e = emb + (size_t)tok * E_SIZE;
    int tid = threadIdx.x;

    float v[3];
    float s = 0.f;
#pragma unroll
    for (int j = 0; j < 3; j++) { v[j] = e[tid + j * 256]; s += v[j]; }

    __shared__ float red[8];
    __shared__ float sh_mu, sh_inv;
#pragma unroll
    for (int o = 16; o > 0; o >>= 1) s += __shfl_xor_sync(0xffffffffu, s, o);
    if ((tid & 31) == 0) red[tid >> 5] = s;
    __syncthreads();
    if (tid == 0) {
        float tot = 0.f;
#pragma unroll
        for (int w = 0; w < 8; w++) tot += red[w];
        sh_mu = tot * (1.f / E_SIZE);
    }
    __syncthreads();
    float mu = sh_mu;

    float s2 = 0.f;
#pragma unroll
    for (int j = 0; j < 3; j++) { float d = v[j] - mu; s2 += d * d; }
#pragma unroll
    for (int o = 16; o > 0; o >>= 1) s2 += __shfl_xor_sync(0xffffffffu, s2, o);
    if ((tid & 31) == 0) red[tid >> 5] = s2;
    __syncthreads();
    if (tid == 0) {
        float tot = 0.f;
#pragma unroll
        for (int w = 0; w < 8; w++) tot += red[w];
        sh_inv = rsqrtf(tot * (1.f / E_SIZE) + LN_EPS);
    }
    __syncthreads();
    float inv = sh_inv;

#pragma unroll
    for (int j = 0; j < 3; j++) {
        int i = tid + j * 256;
        float y = (v[j] - mu) * inv * gamma[i] + beta[i];
        g_x[(size_t)r * E_SIZE + i] = y;
        if (xout) xout[(size_t)r * E_SIZE + i] = y;
    }
}

// ---------------- kernel 1: SGEMM  C[M,N] = A[M,768] @ W[N,768]^T ----------------
// BM=BN=128, BK=16, 256 threads, 8x8 per-thread microtile
__global__ __launch_bounds__(256, 2)
void sgemm768(const float* __restrict__ A,
              const float* __restrict__ W,
              float* __restrict__ C,
              int N, long long ldc) {
    const int K = E_SIZE;
    __shared__ float As[16][128];
    __shared__ float Bs[16][128];

    int tid = threadIdx.x;
    int m0 = blockIdx.y * 128;
    int n0 = blockIdx.x * 128;

    float acc[8][8];
#pragma unroll
    for (int i = 0; i < 8; i++)
#pragma unroll
        for (int j = 0; j < 8; j++) acc[i][j] = 0.f;

    int lrow = tid >> 2;          // 0..63
    int lk   = (tid & 3) * 4;     // 0,4,8,12

    for (int k0 = 0; k0 < K; k0 += 16) {
#pragma unroll
        for (int l = 0; l < 2; l++) {
            int row = lrow + l * 64;
            float4 va = *(const float4*)(A + (size_t)(m0 + row) * K + k0 + lk);
            As[lk + 0][row] = va.x; As[lk + 1][row] = va.y;
            As[lk + 2][row] = va.z; As[lk + 3][row] = va.w;
            float4 vb;
            if (n0 + row < N) vb = *(const float4*)(W + (size_t)(n0 + row) * K + k0 + lk);
            else              vb = make_float4(0.f, 0.f, 0.f, 0.f);
            Bs[lk + 0][row] = vb.x; Bs[lk + 1][row] = vb.y;
            Bs[lk + 2][row] = vb.z; Bs[lk + 3][row] = vb.w;
        }
        __syncthreads();

        int mth = (tid >> 4) * 8;
        int nth = (tid & 15) * 8;
#pragma unroll
        for (int kk = 0; kk < 16; kk++) {
            float4 a0 = *(const float4*)&As[kk][mth];
            float4 a1 = *(const float4*)&As[kk][mth + 4];
            float4 b0 = *(const float4*)&Bs[kk][nth];
            float4 b1 = *(const float4*)&Bs[kk][nth + 4];
            float a[8] = {a0.x, a0.y, a0.z, a0.w, a1.x, a1.y, a1.z, a1.w};
            float b[8] = {b0.x, b0.y, b0.z, b0.w, b1.x, b1.y, b1.z, b1.w};
#pragma unroll
            for (int i = 0; i < 8; i++)
#pragma unroll
                for (int j = 0; j < 8; j++) acc[i][j] = fmaf(a[i], b[j], acc[i][j]);
        }
        __syncthreads();
    }

    int mrow = m0 + (tid >> 4) * 8;
    int ncol = n0 + (tid & 15) * 8;
#pragma unroll
    for (int i = 0; i < 8; i++) {
        float* crow = C + (size_t)(mrow + i) * ldc;
#pragma unroll
        for (int j = 0; j < 8; j++) {
            if (ncol + j < N) crow[ncol + j] = acc[i][j];
        }
    }
}

// ---------------- kernel 2: causal c = q k^T / QK  +  scatter-add into logits ----
// one block per (b,t) row; reads g_q/g_k via device symbols (always valid)
__global__ void scatter_kernel(const int* __restrict__ idx,
                               float* __restrict__ logits) {
    int r = blockIdx.x;
    int b = r >> 10;
    int t = r & 1023;

    __shared__ float4 qs[QK_SIZE / 4];
    const float4* qp = (const float4*)(g_q + (size_t)r * QK_SIZE);
    if (threadIdx.x < QK_SIZE / 4) qs[threadIdx.x] = qp[threadIdx.x];
    __syncthreads();

    const int* ib = idx + b * T_SIZE;
    float* lrow = logits + (size_t)r * V_SIZE;

    for (int s = threadIdx.x; s <= t; s += blockDim.x) {
        const float4* kp = (const float4*)(g_k + (size_t)(b * T_SIZE + s) * QK_SIZE);
        float acc = 0.f;
#pragma unroll 16
        for (int i = 0; i < QK_SIZE / 4; i++) {
            float4 kv = kp[i];
            float4 qv = qs[i];
            acc += qv.x * kv.x + qv.y * kv.y + qv.z * kv.z + qv.w * kv.w;
        }
        atomicAdd(&lrow[ib[s]], acc * (1.0f / QK_SIZE));
    }
}

// ---------------- launch ----------------
extern "C" void kernel_launch(void* const* d_in, const int* in_sizes, int n_in,
                              void* d_out, int out_size) {
    const int*   idx    = (const int*)d_in[0];
    const float* emb_w  = (const float*)d_in[1];
    const float* ln_g   = (const float*)d_in[2];
    const float* ln_b   = (const float*)d_in[3];
    const float* head_w = (const float*)d_in[4];
    const float* head_q = (const float*)d_in[5];
    const float* head_k = (const float*)d_in[6];

    // Resolve device addresses of __device__ scratch (host code must NOT use the
    // symbols directly — that was the R1/R2 bug: garbage host-shadow pointers).
    // cudaGetSymbolAddress is a pure query: no allocation, no stream op, capture-safe.
    void *px = nullptr, *pq = nullptr, *pk = nullptr;
    cudaGetSymbolAddress(&px, g_x);
    cudaGetSymbolAddress(&pq, g_q);
    cudaGetSymbolAddress(&pk, g_k);
    float* xbuf = (float*)px;
    float* qbuf = (float*)pq;
    float* kbuf = (float*)pk;

    float* out    = (float*)d_out;
    float* logits = out;                                   // (B*T, V) at offset 0

    // x output section: derive from out_size so we never write out of bounds.
    const size_t logits_elems = (size_t)M_ROWS * V_SIZE;
    const size_t x_elems      = (size_t)M_ROWS * E_SIZE;
    float* xout = nullptr;
    if ((size_t)out_size >= logits_elems + x_elems)
        xout = out + ((size_t)out_size - x_elems);

    // 1) x = layernorm(emb[idx]); writes g_x and (if present) the x output section
    ln_kernel<<<M_ROWS, 256>>>(idx, emb_w, ln_g, ln_b, xout);

    // 2) q, k projections (4096 x 256 each)
    {
        dim3 grid(QK_SIZE / 128, M_ROWS / 128);
        sgemm768<<<grid, 256>>>(xbuf, head_q, qbuf, QK_SIZE, QK_SIZE);
        sgemm768<<<grid, 256>>>(xbuf, head_k, kbuf, QK_SIZE, QK_SIZE);
    }

    // 3) logits = x @ head_w^T  (writes, so it must precede the scatter adds)
    {
        dim3 grid((V_SIZE + 127) / 128, M_ROWS / 128);
        sgemm768<<<grid, 256>>>(xbuf, head_w, logits, V_SIZE, (long long)V_SIZE);
    }

    // 4) causal copy-scatter: logits[b,t, idx[b,s]] += (q_t . k_s) / QK  for s<=t
    scatter_kernel<<<M_ROWS, 128>>>(idx, logits);
}

// round 6
// speedup vs baseline: 2.8016x; 2.8016x over previous
#include <cuda_runtime.h>
#include <cuda_bf16.h>
#include <cstdint>

#define V_SIZE 50257
#define E_SIZE 768
#define QK_SIZE 256
#define B_SIZE 4
#define T_SIZE 1024
#define M_ROWS (B_SIZE * T_SIZE)   // 4096
#define LN_EPS 1e-5f

#define BM 128
#define BN 128
#define BK 64                        // 64 bf16 = 128B rows (SW128 swizzle)
#define STAGES 3
#define STAGE_BYTES ((BM + BN) * BK * 2)   // 32768
#define SMEM_DYN (STAGES * STAGE_BYTES)    // 98304
#define NPASS 3
#define KITERS (E_SIZE / BK)               // 12
#define TOTAL_ITERS (NPASS * KITERS)       // 36

// ---------------- scratch (static device memory; no allocation) ----------------
__device__ __align__(256) float g_x[M_ROWS * E_SIZE];
__device__ __align__(256) float g_q[M_ROWS * QK_SIZE];
__device__ __align__(256) float g_k[M_ROWS * QK_SIZE];
__device__ __align__(256) __nv_bfloat16 g_xh[M_ROWS * E_SIZE];
__device__ __align__(256) __nv_bfloat16 g_xl[M_ROWS * E_SIZE];
__device__ __align__(256) __nv_bfloat16 g_wh[(size_t)V_SIZE * E_SIZE];
__device__ __align__(256) __nv_bfloat16 g_wl[(size_t)V_SIZE * E_SIZE];

// ---------------- PTX helpers (generic PTX only — no sm_103a features) --------
__device__ __forceinline__ uint32_t smem_u32(const void* p) {
    uint32_t a;
    asm("{ .reg .u64 t; cvta.to.shared.u64 t, %1; cvt.u32.u64 %0, t; }" : "=r"(a) : "l"(p));
    return a;
}
__device__ __forceinline__ void cp16(uint32_t dst, const void* src) {
    asm volatile("cp.async.cg.shared.global [%0], [%1], 16;" :: "r"(dst), "l"(src));
}
#define CP_COMMIT() asm volatile("cp.async.commit_group;" ::: "memory")
#define CP_WAIT1()  asm volatile("cp.async.wait_group 1;" ::: "memory")
#define CP_WAIT0()  asm volatile("cp.async.wait_group 0;" ::: "memory")

__device__ __forceinline__ void ldsm_x4(uint32_t& r0, uint32_t& r1, uint32_t& r2, uint32_t& r3,
                                        uint32_t addr) {
    asm volatile("ldmatrix.sync.aligned.m8n8.x4.shared.b16 {%0,%1,%2,%3}, [%4];"
                 : "=r"(r0), "=r"(r1), "=r"(r2), "=r"(r3) : "r"(addr));
}
__device__ __forceinline__ void mma16816(float* d, const uint32_t* a, const uint32_t* b) {
    asm volatile("mma.sync.aligned.m16n8k16.row.col.f32.bf16.bf16.f32 "
                 "{%0,%1,%2,%3}, {%4,%5,%6,%7}, {%8,%9}, {%0,%1,%2,%3};"
                 : "+f"(d[0]), "+f"(d[1]), "+f"(d[2]), "+f"(d[3])
                 : "r"(a[0]), "r"(a[1]), "r"(a[2]), "r"(a[3]), "r"(b[0]), "r"(b[1]));
}

// swizzled byte offset inside a tile with 128B rows: row r, 16B-chunk c
__device__ __forceinline__ uint32_t swz(int r, int c) {
    return (uint32_t)(r * 128 + ((c ^ (r & 7)) << 4));
}

// ---------------- kernel 0: gather + layernorm (+ bf16 hi/lo split of x) ------
__global__ void ln_kernel(const int* __restrict__ idx,
                          const float* __restrict__ emb,
                          const float* __restrict__ gamma,
                          const float* __restrict__ beta,
                          float* __restrict__ xout) {
    int r = blockIdx.x;
    int tok = idx[r];
    const float* e = emb + (size_t)tok * E_SIZE;
    int tid = threadIdx.x;

    float v[3];
    float s = 0.f;
#pragma unroll
    for (int j = 0; j < 3; j++) { v[j] = e[tid + j * 256]; s += v[j]; }

    __shared__ float red[8];
    __shared__ float sh_mu, sh_inv;
#pragma unroll
    for (int o = 16; o > 0; o >>= 1) s += __shfl_xor_sync(0xffffffffu, s, o);
    if ((tid & 31) == 0) red[tid >> 5] = s;
    __syncthreads();
    if (tid == 0) {
        float tot = 0.f;
#pragma unroll
        for (int w = 0; w < 8; w++) tot += red[w];
        sh_mu = tot * (1.f / E_SIZE);
    }
    __syncthreads();
    float mu = sh_mu;

    float s2 = 0.f;
#pragma unroll
    for (int j = 0; j < 3; j++) { float d = v[j] - mu; s2 += d * d; }
#pragma unroll
    for (int o = 16; o > 0; o >>= 1) s2 += __shfl_xor_sync(0xffffffffu, s2, o);
    if ((tid & 31) == 0) red[tid >> 5] = s2;
    __syncthreads();
    if (tid == 0) {
        float tot = 0.f;
#pragma unroll
        for (int w = 0; w < 8; w++) tot += red[w];
        sh_inv = rsqrtf(tot * (1.f / E_SIZE) + LN_EPS);
    }
    __syncthreads();
    float inv = sh_inv;

#pragma unroll
    for (int j = 0; j < 3; j++) {
        int i = tid + j * 256;
        float y = (v[j] - mu) * inv * gamma[i] + beta[i];
        size_t o = (size_t)r * E_SIZE + i;
        g_x[o] = y;
        __nv_bfloat16 h = __float2bfloat16(y);
        g_xh[o] = h;
        g_xl[o] = __float2bfloat16(y - __bfloat162float(h));
        if (xout) xout[o] = y;
    }
}

// ---------------- kernel 0b: split head_w into bf16 hi/lo ----------------
__global__ void wsplit_kernel(const float* __restrict__ w) {
    size_t i2 = (size_t)blockIdx.x * blockDim.x + threadIdx.x;
    size_t n2 = (size_t)V_SIZE * E_SIZE / 2;
    if (i2 >= n2) return;
    float2 v = ((const float2*)w)[i2];
    __nv_bfloat16 h0 = __float2bfloat16(v.x);
    __nv_bfloat16 h1 = __float2bfloat16(v.y);
    __nv_bfloat16 l0 = __float2bfloat16(v.x - __bfloat162float(h0));
    __nv_bfloat16 l1 = __float2bfloat16(v.y - __bfloat162float(h1));
    ((__nv_bfloat162*)g_wh)[i2] = __nv_bfloat162(h0, h1);
    ((__nv_bfloat162*)g_wl)[i2] = __nv_bfloat162(l0, l1);
}

// ---------------- kernel 1: bf16 mma.sync vocab GEMM (3-pass split) ----------
// C[m0:+128, n0:+128] = xh*wh^T + xl*wh^T + xh*wl^T   (fp32 accum)
__global__ __launch_bounds__(256)
void mma_gemm_kernel(const __nv_bfloat16* __restrict__ xh,
                     const __nv_bfloat16* __restrict__ xl,
                     const __nv_bfloat16* __restrict__ wh,
                     const __nv_bfloat16* __restrict__ wl,
                     float* __restrict__ C) {
    extern __shared__ char smem[];
    const uint32_t sb = smem_u32(smem);

    const int tid = threadIdx.x;
    const int wid = tid >> 5;
    const int lane = tid & 31;
    const int m0 = blockIdx.x * BM;
    const int n0 = blockIdx.y * BN;

    const int wm = (wid & 3) * 32;   // warp M offset (4 warps in M)
    const int wn = (wid >> 2) * 64;  // warp N offset (2 warps in N)

    float acc[2][8][4];
#pragma unroll
    for (int mi = 0; mi < 2; mi++)
#pragma unroll
        for (int ni = 0; ni < 8; ni++)
#pragma unroll
            for (int q = 0; q < 4; q++) acc[mi][ni][q] = 0.f;

    // ---- stage loader: t = global iter (pass = t/12, kbase = (t%12)*64) ----
    auto load_stage = [&](int t, int s) {
        int p = t / KITERS;
        int kbase = (t % KITERS) * BK;
        const __nv_bfloat16* Ap = (p == 1) ? xl : xh;
        const __nv_bfloat16* Bp = (p == 2) ? wl : wh;
        uint32_t a_s = sb + s * STAGE_BYTES;
        uint32_t b_s = a_s + BM * BK * 2;
        // A: 128 rows x 8 chunks(16B) = 1024 -> 4 per thread
#pragma unroll
        for (int j = 0; j < 4; j++) {
            int id = tid + j * 256;
            int r = id >> 3, c = id & 7;
            cp16(a_s + swz(r, c), Ap + (size_t)(m0 + r) * E_SIZE + kbase + c * 8);
        }
        // B: 128 rows x 8 chunks = 1024 -> 4 per thread (clamp tail rows)
#pragma unroll
        for (int j = 0; j < 4; j++) {
            int id = tid + j * 256;
            int r = id >> 3, c = id & 7;
            int gn = n0 + r;
            if (gn > V_SIZE - 1) gn = V_SIZE - 1;
            cp16(b_s + swz(r, c), Bp + (size_t)gn * E_SIZE + kbase + c * 8);
        }
        CP_COMMIT();
    };

    load_stage(0, 0);
    load_stage(1, 1);

    const int lrl = lane & 7;          // ldmatrix row-within-matrix
    const int lmat = lane >> 3;        // ldmatrix matrix id 0..3

    for (int t = 0; t < TOTAL_ITERS; t++) {
        if (t < TOTAL_ITERS - 2) { CP_WAIT1(); } else { CP_WAIT0(); }
        __syncthreads();
        if (t + 2 < TOTAL_ITERS) load_stage(t + 2, (t + 2) % STAGES);

        int s = t % STAGES;
        uint32_t a_s = sb + s * STAGE_BYTES;
        uint32_t b_s = a_s + BM * BK * 2;

#pragma unroll
        for (int kk = 0; kk < 4; kk++) {          // 4 x k16 per BK=64
            int cbase = kk * 2;                    // 16B-chunk base for this k16
            // A fragments: two m16 tiles (wm, wm+16)
            uint32_t afr[2][4];
#pragma unroll
            for (int mi = 0; mi < 2; mi++) {
                int r = wm + mi * 16 + lrl + (lmat & 1) * 8;
                int c = cbase + (lmat >> 1);
                ldsm_x4(afr[mi][0], afr[mi][1], afr[mi][2], afr[mi][3], a_s + swz(r, c));
            }
            // B fragments: 8 n8 tiles as 4 x ldmatrix.x4 (pairs)
            uint32_t bfr[8][2];
#pragma unroll
            for (int pr = 0; pr < 4; pr++) {
                int r = wn + pr * 16 + lrl + (lmat >> 1) * 8;
                int c = cbase + (lmat & 1);
                uint32_t q0, q1, q2, q3;
                ldsm_x4(q0, q1, q2, q3, b_s + swz(r, c));
                bfr[pr * 2 + 0][0] = q0; bfr[pr * 2 + 0][1] = q1;
                bfr[pr * 2 + 1][0] = q2; bfr[pr * 2 + 1][1] = q3;
            }
#pragma unroll
            for (int mi = 0; mi < 2; mi++)
#pragma unroll
                for (int ni = 0; ni < 8; ni++)
                    mma16816(acc[mi][ni], afr[mi], bfr[ni]);
        }
        __syncthreads();
    }

    // ---- epilogue: scalar stores (V_SIZE=50257 is ODD -> odd rows are only
    // 4B-aligned; float2/float4 stores trap with misaligned address) ----
    const int lr = lane >> 2;          // 0..7
    const int lc = (lane & 3) * 2;     // 0,2,4,6
#pragma unroll
    for (int mi = 0; mi < 2; mi++) {
        int row0 = m0 + wm + mi * 16 + lr;
#pragma unroll
        for (int ni = 0; ni < 8; ni++) {
            int col = n0 + wn + ni * 8 + lc;
            float* d0 = C + (size_t)row0 * V_SIZE + col;
            float* d1 = C + (size_t)(row0 + 8) * V_SIZE + col;
            if (col < V_SIZE)     { d0[0] = acc[mi][ni][0]; d1[0] = acc[mi][ni][2]; }
            if (col + 1 < V_SIZE) { d0[1] = acc[mi][ni][1]; d1[1] = acc[mi][ni][3]; }
        }
    }
}

// ---------------- kernel 2: fp32 SGEMM for q/k projections ----------------
__global__ __launch_bounds__(256, 2)
void sgemm768(const float* __restrict__ A,
              const float* __restrict__ W,
              float* __restrict__ C,
              int N, long long ldc) {
    const int K = E_SIZE;
    __shared__ float As[16][128];
    __shared__ float Bs[16][128];

    int tid = threadIdx.x;
    int m0 = blockIdx.y * 128;
    int n0 = blockIdx.x * 128;

    float acc[8][8];
#pragma unroll
    for (int i = 0; i < 8; i++)
#pragma unroll
        for (int j = 0; j < 8; j++) acc[i][j] = 0.f;

    int lrow = tid >> 2;
    int lk = (tid & 3) * 4;

    for (int k0 = 0; k0 < K; k0 += 16) {
#pragma unroll
        for (int l = 0; l < 2; l++) {
            int row = lrow + l * 64;
            float4 va = *(const float4*)(A + (size_t)(m0 + row) * K + k0 + lk);
            As[lk + 0][row] = va.x; As[lk + 1][row] = va.y;
            As[lk + 2][row] = va.z; As[lk + 3][row] = va.w;
            float4 vb;
            if (n0 + row < N) vb = *(const float4*)(W + (size_t)(n0 + row) * K + k0 + lk);
            else              vb = make_float4(0.f, 0.f, 0.f, 0.f);
            Bs[lk + 0][row] = vb.x; Bs[lk + 1][row] = vb.y;
            Bs[lk + 2][row] = vb.z; Bs[lk + 3][row] = vb.w;
        }
        __syncthreads();

        int mth = (tid >> 4) * 8;
        int nth = (tid & 15) * 8;
#pragma unroll
        for (int kk = 0; kk < 16; kk++) {
            float4 a0 = *(const float4*)&As[kk][mth];
            float4 a1 = *(const float4*)&As[kk][mth + 4];
            float4 b0 = *(const float4*)&Bs[kk][nth];
            float4 b1 = *(const float4*)&Bs[kk][nth + 4];
            float a[8] = {a0.x, a0.y, a0.z, a0.w, a1.x, a1.y, a1.z, a1.w};
            float b[8] = {b0.x, b0.y, b0.z, b0.w, b1.x, b1.y, b1.z, b1.w};
#pragma unroll
            for (int i = 0; i < 8; i++)
#pragma unroll
                for (int j = 0; j < 8; j++) acc[i][j] = fmaf(a[i], b[j], acc[i][j]);
        }
        __syncthreads();
    }

    int mrow = m0 + (tid >> 4) * 8;
    int ncol = n0 + (tid & 15) * 8;
#pragma unroll
    for (int i = 0; i < 8; i++) {
        float* crow = C + (size_t)(mrow + i) * ldc;
#pragma unroll
        for (int j = 0; j < 8; j++) {
            if (ncol + j < N) crow[ncol + j] = acc[i][j];
        }
    }
}

// ---------------- kernel 3: causal c = q k^T / QK  + scatter-add into logits --
__global__ void scatter_kernel(const int* __restrict__ idx,
                               float* __restrict__ logits) {
    int r = blockIdx.x;
    int b = r >> 10;
    int t = r & 1023;

    __shared__ float4 qs[QK_SIZE / 4];
    const float4* qp = (const float4*)(g_q + (size_t)r * QK_SIZE);
    if (threadIdx.x < QK_SIZE / 4) qs[threadIdx.x] = qp[threadIdx.x];
    __syncthreads();

    const int* ib = idx + b * T_SIZE;
    float* lrow = logits + (size_t)r * V_SIZE;

    for (int s = threadIdx.x; s <= t; s += blockDim.x) {
        const float4* kp = (const float4*)(g_k + (size_t)(b * T_SIZE + s) * QK_SIZE);
        float acc = 0.f;
#pragma unroll 16
        for (int i = 0; i < QK_SIZE / 4; i++) {
            float4 kv = kp[i];
            float4 qv = qs[i];
            acc += qv.x * kv.x + qv.y * kv.y + qv.z * kv.z + qv.w * kv.w;
        }
        atomicAdd(&lrow[ib[s]], acc * (1.0f / QK_SIZE));
    }
}

// ---------------- launch ----------------
extern "C" void kernel_launch(void* const* d_in, const int* in_sizes, int n_in,
                              void* d_out, int out_size) {
    const int*   idx    = (const int*)d_in[0];
    const float* emb_w  = (const float*)d_in[1];
    const float* ln_g   = (const float*)d_in[2];
    const float* ln_b   = (const float*)d_in[3];
    const float* head_w = (const float*)d_in[4];
    const float* head_q = (const float*)d_in[5];
    const float* head_k = (const float*)d_in[6];

    // Resolve device addresses of __device__ scratch (NEVER pass symbols from host).
    void *px, *pq, *pk, *pxh, *pxl, *pwh, *pwl;
    cudaGetSymbolAddress(&px, g_x);
    cudaGetSymbolAddress(&pq, g_q);
    cudaGetSymbolAddress(&pk, g_k);
    cudaGetSymbolAddress(&pxh, g_xh);
    cudaGetSymbolAddress(&pxl, g_xl);
    cudaGetSymbolAddress(&pwh, g_wh);
    cudaGetSymbolAddress(&pwl, g_wl);

    float* out    = (float*)d_out;
    float* logits = out;

    const size_t logits_elems = (size_t)M_ROWS * V_SIZE;
    const size_t x_elems      = (size_t)M_ROWS * E_SIZE;
    float* xout = nullptr;
    if ((size_t)out_size >= logits_elems + x_elems)
        xout = out + ((size_t)out_size - x_elems);

    // 1) x = layernorm(emb[idx]) (+ bf16 hi/lo split of x)
    ln_kernel<<<M_ROWS, 256>>>(idx, emb_w, ln_g, ln_b, xout);

    // 1b) split head_w into bf16 hi/lo
    {
        size_t n2 = (size_t)V_SIZE * E_SIZE / 2;
        wsplit_kernel<<<(unsigned)((n2 + 255) / 256), 256>>>(head_w);
    }

    // 2) q, k projections (fp32, small)
    {
        dim3 grid(QK_SIZE / 128, M_ROWS / 128);
        sgemm768<<<grid, 256>>>((float*)px, head_q, (float*)pq, QK_SIZE, QK_SIZE);
        sgemm768<<<grid, 256>>>((float*)px, head_k, (float*)pk, QK_SIZE, QK_SIZE);
    }

    // 3) logits = x @ head_w^T via bf16 mma.sync 3-pass split
    {
        cudaFuncSetAttribute(mma_gemm_kernel, cudaFuncAttributeMaxDynamicSharedMemorySize, SMEM_DYN);
        dim3 grid(M_ROWS / BM, (V_SIZE + BN - 1) / BN);   // M fastest: B-tile L2 reuse
        mma_gemm_kernel<<<grid, 256, SMEM_DYN>>>(
            (const __nv_bfloat16*)pxh, (const __nv_bfloat16*)pxl,
            (const __nv_bfloat16*)pwh, (const __nv_bfloat16*)pwl, logits);
    }

    // 4) causal copy-scatter
    scatter_kernel<<<M_ROWS, 128>>>(idx, logits);
}

// round 7
// speedup vs baseline: 3.1297x; 1.1171x over previous
#include <cuda_runtime.h>
#include <cuda_bf16.h>
#include <cstdint>

#define V_SIZE 50257
#define E_SIZE 768
#define QK_SIZE 256
#define B_SIZE 4
#define T_SIZE 1024
#define M_ROWS (B_SIZE * T_SIZE)   // 4096
#define LN_EPS 1e-5f

#define BM 128
#define BN 128
#define BK 64                        // 64 bf16 = 128B rows (SW128 swizzle)
#define STAGES 3
#define STAGE_BYTES ((BM + BN) * BK * 2)   // 32768
#define SMEM_DYN (STAGES * STAGE_BYTES)    // 98304
#define NPASS 3
#define KITERS (E_SIZE / BK)               // 12
#define TOTAL_ITERS (NPASS * KITERS)       // 36

// ---------------- scratch (static device memory; no allocation) ----------------
__device__ __align__(256) float g_x[M_ROWS * E_SIZE];
__device__ __align__(256) float g_q[M_ROWS * QK_SIZE];
__device__ __align__(256) float g_k[M_ROWS * QK_SIZE];
__device__ __align__(256) float g_c[(size_t)B_SIZE * T_SIZE * T_SIZE];  // 16MB QK^T
__device__ __align__(256) __nv_bfloat16 g_xh[M_ROWS * E_SIZE];
__device__ __align__(256) __nv_bfloat16 g_xl[M_ROWS * E_SIZE];
__device__ __align__(256) __nv_bfloat16 g_wh[(size_t)V_SIZE * E_SIZE];
__device__ __align__(256) __nv_bfloat16 g_wl[(size_t)V_SIZE * E_SIZE];

// ---------------- PTX helpers (generic PTX only — no sm_103a features) --------
__device__ __forceinline__ uint32_t smem_u32(const void* p) {
    uint32_t a;
    asm("{ .reg .u64 t; cvta.to.shared.u64 t, %1; cvt.u32.u64 %0, t; }" : "=r"(a) : "l"(p));
    return a;
}
__device__ __forceinline__ void cp16(uint32_t dst, const void* src) {
    asm volatile("cp.async.cg.shared.global [%0], [%1], 16;" :: "r"(dst), "l"(src));
}
#define CP_COMMIT() asm volatile("cp.async.commit_group;" ::: "memory")
#define CP_WAIT1()  asm volatile("cp.async.wait_group 1;" ::: "memory")
#define CP_WAIT0()  asm volatile("cp.async.wait_group 0;" ::: "memory")

__device__ __forceinline__ void ldsm_x4(uint32_t& r0, uint32_t& r1, uint32_t& r2, uint32_t& r3,
                                        uint32_t addr) {
    asm volatile("ldmatrix.sync.aligned.m8n8.x4.shared.b16 {%0,%1,%2,%3}, [%4];"
                 : "=r"(r0), "=r"(r1), "=r"(r2), "=r"(r3) : "r"(addr));
}
__device__ __forceinline__ void mma16816(float* d, const uint32_t* a, const uint32_t* b) {
    asm volatile("mma.sync.aligned.m16n8k16.row.col.f32.bf16.bf16.f32 "
                 "{%0,%1,%2,%3}, {%4,%5,%6,%7}, {%8,%9}, {%0,%1,%2,%3};"
                 : "+f"(d[0]), "+f"(d[1]), "+f"(d[2]), "+f"(d[3])
                 : "r"(a[0]), "r"(a[1]), "r"(a[2]), "r"(a[3]), "r"(b[0]), "r"(b[1]));
}

// swizzled byte offset inside a tile with 128B rows: row r, 16B-chunk c
__device__ __forceinline__ uint32_t swz(int r, int c) {
    return (uint32_t)(r * 128 + ((c ^ (r & 7)) << 4));
}

// ---------------- kernel 0: gather + layernorm (+ bf16 hi/lo split of x) ------
__global__ void ln_kernel(const int* __restrict__ idx,
                          const float* __restrict__ emb,
                          const float* __restrict__ gamma,
                          const float* __restrict__ beta,
                          float* __restrict__ xout) {
    int r = blockIdx.x;
    int tok = idx[r];
    const float* e = emb + (size_t)tok * E_SIZE;
    int tid = threadIdx.x;

    float v[3];
    float s = 0.f;
#pragma unroll
    for (int j = 0; j < 3; j++) { v[j] = e[tid + j * 256]; s += v[j]; }

    __shared__ float red[8];
    __shared__ float sh_mu, sh_inv;
#pragma unroll
    for (int o = 16; o > 0; o >>= 1) s += __shfl_xor_sync(0xffffffffu, s, o);
    if ((tid & 31) == 0) red[tid >> 5] = s;
    __syncthreads();
    if (tid == 0) {
        float tot = 0.f;
#pragma unroll
        for (int w = 0; w < 8; w++) tot += red[w];
        sh_mu = tot * (1.f / E_SIZE);
    }
    __syncthreads();
    float mu = sh_mu;

    float s2 = 0.f;
#pragma unroll
    for (int j = 0; j < 3; j++) { float d = v[j] - mu; s2 += d * d; }
#pragma unroll
    for (int o = 16; o > 0; o >>= 1) s2 += __shfl_xor_sync(0xffffffffu, s2, o);
    if ((tid & 31) == 0) red[tid >> 5] = s2;
    __syncthreads();
    if (tid == 0) {
        float tot = 0.f;
#pragma unroll
        for (int w = 0; w < 8; w++) tot += red[w];
        sh_inv = rsqrtf(tot * (1.f / E_SIZE) + LN_EPS);
    }
    __syncthreads();
    float inv = sh_inv;

#pragma unroll
    for (int j = 0; j < 3; j++) {
        int i = tid + j * 256;
        float y = (v[j] - mu) * inv * gamma[i] + beta[i];
        size_t o = (size_t)r * E_SIZE + i;
        g_x[o] = y;
        __nv_bfloat16 h = __float2bfloat16(y);
        g_xh[o] = h;
        g_xl[o] = __float2bfloat16(y - __bfloat162float(h));
        if (xout) xout[o] = y;
    }
}

// ---------------- kernel 0b: split head_w into bf16 hi/lo ----------------
__global__ void wsplit_kernel(const float* __restrict__ w) {
    size_t i2 = (size_t)blockIdx.x * blockDim.x + threadIdx.x;
    size_t n2 = (size_t)V_SIZE * E_SIZE / 2;
    if (i2 >= n2) return;
    float2 v = ((const float2*)w)[i2];
    __nv_bfloat16 h0 = __float2bfloat16(v.x);
    __nv_bfloat16 h1 = __float2bfloat16(v.y);
    __nv_bfloat16 l0 = __float2bfloat16(v.x - __bfloat162float(h0));
    __nv_bfloat16 l1 = __float2bfloat16(v.y - __bfloat162float(h1));
    ((__nv_bfloat162*)g_wh)[i2] = __nv_bfloat162(h0, h1);
    ((__nv_bfloat162*)g_wl)[i2] = __nv_bfloat162(l0, l1);
}

// ---------------- kernel 1: bf16 mma.sync vocab GEMM (3-pass split) ----------
__global__ __launch_bounds__(256)
void mma_gemm_kernel(const __nv_bfloat16* __restrict__ xh,
                     const __nv_bfloat16* __restrict__ xl,
                     const __nv_bfloat16* __restrict__ wh,
                     const __nv_bfloat16* __restrict__ wl,
                     float* __restrict__ C) {
    extern __shared__ char smem[];
    const uint32_t sb = smem_u32(smem);

    const int tid = threadIdx.x;
    const int wid = tid >> 5;
    const int lane = tid & 31;
    const int m0 = blockIdx.x * BM;
    const int n0 = blockIdx.y * BN;

    const int wm = (wid & 3) * 32;   // warp M offset (4 warps in M)
    const int wn = (wid >> 2) * 64;  // warp N offset (2 warps in N)

    float acc[2][8][4];
#pragma unroll
    for (int mi = 0; mi < 2; mi++)
#pragma unroll
        for (int ni = 0; ni < 8; ni++)
#pragma unroll
            for (int q = 0; q < 4; q++) acc[mi][ni][q] = 0.f;

    auto load_stage = [&](int t, int s) {
        int p = t / KITERS;
        int kbase = (t % KITERS) * BK;
        const __nv_bfloat16* Ap = (p == 1) ? xl : xh;
        const __nv_bfloat16* Bp = (p == 2) ? wl : wh;
        uint32_t a_s = sb + s * STAGE_BYTES;
        uint32_t b_s = a_s + BM * BK * 2;
#pragma unroll
        for (int j = 0; j < 4; j++) {
            int id = tid + j * 256;
            int r = id >> 3, c = id & 7;
            cp16(a_s + swz(r, c), Ap + (size_t)(m0 + r) * E_SIZE + kbase + c * 8);
        }
#pragma unroll
        for (int j = 0; j < 4; j++) {
            int id = tid + j * 256;
            int r = id >> 3, c = id & 7;
            int gn = n0 + r;
            if (gn > V_SIZE - 1) gn = V_SIZE - 1;
            cp16(b_s + swz(r, c), Bp + (size_t)gn * E_SIZE + kbase + c * 8);
        }
        CP_COMMIT();
    };

    load_stage(0, 0);
    load_stage(1, 1);

    const int lrl = lane & 7;
    const int lmat = lane >> 3;

    for (int t = 0; t < TOTAL_ITERS; t++) {
        if (t < TOTAL_ITERS - 2) { CP_WAIT1(); } else { CP_WAIT0(); }
        __syncthreads();
        if (t + 2 < TOTAL_ITERS) load_stage(t + 2, (t + 2) % STAGES);

        int s = t % STAGES;
        uint32_t a_s = sb + s * STAGE_BYTES;
        uint32_t b_s = a_s + BM * BK * 2;

#pragma unroll
        for (int kk = 0; kk < 4; kk++) {
            int cbase = kk * 2;
            uint32_t afr[2][4];
#pragma unroll
            for (int mi = 0; mi < 2; mi++) {
                int r = wm + mi * 16 + lrl + (lmat & 1) * 8;
                int c = cbase + (lmat >> 1);
                ldsm_x4(afr[mi][0], afr[mi][1], afr[mi][2], afr[mi][3], a_s + swz(r, c));
            }
            uint32_t bfr[8][2];
#pragma unroll
            for (int pr = 0; pr < 4; pr++) {
                int r = wn + pr * 16 + lrl + (lmat >> 1) * 8;
                int c = cbase + (lmat & 1);
                uint32_t q0, q1, q2, q3;
                ldsm_x4(q0, q1, q2, q3, b_s + swz(r, c));
                bfr[pr * 2 + 0][0] = q0; bfr[pr * 2 + 0][1] = q1;
                bfr[pr * 2 + 1][0] = q2; bfr[pr * 2 + 1][1] = q3;
            }
#pragma unroll
            for (int mi = 0; mi < 2; mi++)
#pragma unroll
                for (int ni = 0; ni < 8; ni++)
                    mma16816(acc[mi][ni], afr[mi], bfr[ni]);
        }
        __syncthreads();
    }

    // scalar stores: V_SIZE odd -> odd rows only 4B-aligned
    const int lr = lane >> 2;
    const int lc = (lane & 3) * 2;
#pragma unroll
    for (int mi = 0; mi < 2; mi++) {
        int row0 = m0 + wm + mi * 16 + lr;
#pragma unroll
        for (int ni = 0; ni < 8; ni++) {
            int col = n0 + wn + ni * 8 + lc;
            float* d0 = C + (size_t)row0 * V_SIZE + col;
            float* d1 = C + (size_t)(row0 + 8) * V_SIZE + col;
            if (col < V_SIZE)     { d0[0] = acc[mi][ni][0]; d1[0] = acc[mi][ni][2]; }
            if (col + 1 < V_SIZE) { d0[1] = acc[mi][ni][1]; d1[1] = acc[mi][ni][3]; }
        }
    }
}

// ---------------- kernel 2: fused q+k projections (fp32 SGEMM, z selects) -----
__global__ __launch_bounds__(256, 2)
void qkproj_kernel(const float* __restrict__ A,
                   const float* __restrict__ Wq,
                   const float* __restrict__ Wk) {
    const int K = E_SIZE;
    __shared__ float As[16][128];
    __shared__ float Bs[16][128];

    const float* W = blockIdx.z ? Wk : Wq;
    float* C = blockIdx.z ? g_k : g_q;

    int tid = threadIdx.x;
    int m0 = blockIdx.y * 128;
    int n0 = blockIdx.x * 128;

    float acc[8][8];
#pragma unroll
    for (int i = 0; i < 8; i++)
#pragma unroll
        for (int j = 0; j < 8; j++) acc[i][j] = 0.f;

    int lrow = tid >> 2;
    int lk = (tid & 3) * 4;

    for (int k0 = 0; k0 < K; k0 += 16) {
#pragma unroll
        for (int l = 0; l < 2; l++) {
            int row = lrow + l * 64;
            float4 va = *(const float4*)(A + (size_t)(m0 + row) * K + k0 + lk);
            As[lk + 0][row] = va.x; As[lk + 1][row] = va.y;
            As[lk + 2][row] = va.z; As[lk + 3][row] = va.w;
            float4 vb = *(const float4*)(W + (size_t)(n0 + row) * K + k0 + lk);
            Bs[lk + 0][row] = vb.x; Bs[lk + 1][row] = vb.y;
            Bs[lk + 2][row] = vb.z; Bs[lk + 3][row] = vb.w;
        }
        __syncthreads();

        int mth = (tid >> 4) * 8;
        int nth = (tid & 15) * 8;
#pragma unroll
        for (int kk = 0; kk < 16; kk++) {
            float4 a0 = *(const float4*)&As[kk][mth];
            float4 a1 = *(const float4*)&As[kk][mth + 4];
            float4 b0 = *(const float4*)&Bs[kk][nth];
            float4 b1 = *(const float4*)&Bs[kk][nth + 4];
            float a[8] = {a0.x, a0.y, a0.z, a0.w, a1.x, a1.y, a1.z, a1.w};
            float b[8] = {b0.x, b0.y, b0.z, b0.w, b1.x, b1.y, b1.z, b1.w};
#pragma unroll
            for (int i = 0; i < 8; i++)
#pragma unroll
                for (int j = 0; j < 8; j++) acc[i][j] = fmaf(a[i], b[j], acc[i][j]);
        }
        __syncthreads();
    }

    int mrow = m0 + (tid >> 4) * 8;
    int ncol = n0 + (tid & 15) * 8;
#pragma unroll
    for (int i = 0; i < 8; i++) {
        float* crow = C + (size_t)(mrow + i) * QK_SIZE;
#pragma unroll
        for (int j = 0; j < 8; j++) crow[ncol + j] = acc[i][j];
    }
}

// ---------------- kernel 3: c = q k^T  (lower-triangle tiles only) ------------
// per batch: 8x8 M/N tile grid, only nt<=mt (36 tiles); 4 batches -> 144 CTAs
__global__ __launch_bounds__(256, 2)
void qk_gemm_kernel() {
    int bx = blockIdx.x;
    int b = bx / 36;
    int p = bx % 36;
    // decode lower-triangle pair (mt, nt), nt<=mt, from p
    int mt = 0;
    while ((mt + 1) * (mt + 2) / 2 <= p) mt++;
    int nt = p - mt * (mt + 1) / 2;

    const float* Aq = g_q + (size_t)b * T_SIZE * QK_SIZE;
    const float* Bk = g_k + (size_t)b * T_SIZE * QK_SIZE;
    float* C = g_c + (size_t)b * T_SIZE * T_SIZE;

    __shared__ float As[16][128];
    __shared__ float Bs[16][128];

    int tid = threadIdx.x;
    int m0 = mt * 128;
    int n0 = nt * 128;

    float acc[8][8];
#pragma unroll
    for (int i = 0; i < 8; i++)
#pragma unroll
        for (int j = 0; j < 8; j++) acc[i][j] = 0.f;

    int lrow = tid >> 2;
    int lk = (tid & 3) * 4;

    for (int k0 = 0; k0 < QK_SIZE; k0 += 16) {
#pragma unroll
        for (int l = 0; l < 2; l++) {
            int row = lrow + l * 64;
            float4 va = *(const float4*)(Aq + (size_t)(m0 + row) * QK_SIZE + k0 + lk);
            As[lk + 0][row] = va.x; As[lk + 1][row] = va.y;
            As[lk + 2][row] = va.z; As[lk + 3][row] = va.w;
            float4 vb = *(const float4*)(Bk + (size_t)(n0 + row) * QK_SIZE + k0 + lk);
            Bs[lk + 0][row] = vb.x; Bs[lk + 1][row] = vb.y;
            Bs[lk + 2][row] = vb.z; Bs[lk + 3][row] = vb.w;
        }
        __syncthreads();

        int mth = (tid >> 4) * 8;
        int nth = (tid & 15) * 8;
#pragma unroll
        for (int kk = 0; kk < 16; kk++) {
            float4 a0 = *(const float4*)&As[kk][mth];
            float4 a1 = *(const float4*)&As[kk][mth + 4];
            float4 b0 = *(const float4*)&Bs[kk][nth];
            float4 b1 = *(const float4*)&Bs[kk][nth + 4];
            float a[8] = {a0.x, a0.y, a0.z, a0.w, a1.x, a1.y, a1.z, a1.w};
            float b[8] = {b0.x, b0.y, b0.z, b0.w, b1.x, b1.y, b1.z, b1.w};
#pragma unroll
            for (int i = 0; i < 8; i++)
#pragma unroll
                for (int j = 0; j < 8; j++) acc[i][j] = fmaf(a[i], b[j], acc[i][j]);
        }
        __syncthreads();
    }

    int mrow = m0 + (tid >> 4) * 8;
    int ncol = n0 + (tid & 15) * 8;
#pragma unroll
    for (int i = 0; i < 8; i++) {
        float* crow = C + (size_t)(mrow + i) * T_SIZE;
#pragma unroll
        for (int j = 0; j < 8; j++) crow[ncol + j] = acc[i][j];
    }
}

// ---------------- kernel 4: scatter-add  logits[r, idx[b,s]] += c[r,s]/QK -----
__global__ void scatter_kernel(const int* __restrict__ idx,
                               float* __restrict__ logits) {
    int r = blockIdx.x;
    int b = r >> 10;
    int t = r & 1023;

    const float* crow = g_c + (size_t)b * T_SIZE * T_SIZE + (size_t)t * T_SIZE;
    const int* ib = idx + b * T_SIZE;
    float* lrow = logits + (size_t)r * V_SIZE;

    for (int s = threadIdx.x; s <= t; s += blockDim.x)
        atomicAdd(&lrow[ib[s]], crow[s] * (1.0f / QK_SIZE));
}

// ---------------- launch ----------------
extern "C" void kernel_launch(void* const* d_in, const int* in_sizes, int n_in,
                              void* d_out, int out_size) {
    const int*   idx    = (const int*)d_in[0];
    const float* emb_w  = (const float*)d_in[1];
    const float* ln_g   = (const float*)d_in[2];
    const float* ln_b   = (const float*)d_in[3];
    const float* head_w = (const float*)d_in[4];
    const float* head_q = (const float*)d_in[5];
    const float* head_k = (const float*)d_in[6];

    void *px, *pxh, *pxl, *pwh, *pwl;
    cudaGetSymbolAddress(&px, g_x);
    cudaGetSymbolAddress(&pxh, g_xh);
    cudaGetSymbolAddress(&pxl, g_xl);
    cudaGetSymbolAddress(&pwh, g_wh);
    cudaGetSymbolAddress(&pwl, g_wl);

    float* out    = (float*)d_out;
    float* logits = out;

    const size_t logits_elems = (size_t)M_ROWS * V_SIZE;
    const size_t x_elems      = (size_t)M_ROWS * E_SIZE;
    float* xout = nullptr;
    if ((size_t)out_size >= logits_elems + x_elems)
        xout = out + ((size_t)out_size - x_elems);

    // 1) x = layernorm(emb[idx]) (+ bf16 hi/lo split of x)
    ln_kernel<<<M_ROWS, 256>>>(idx, emb_w, ln_g, ln_b, xout);

    // 1b) split head_w into bf16 hi/lo
    {
        size_t n2 = (size_t)V_SIZE * E_SIZE / 2;
        wsplit_kernel<<<(unsigned)((n2 + 255) / 256), 256>>>(head_w);
    }

    // 2) fused q+k projections (z dim selects target) — 128 concurrent CTAs
    {
        dim3 grid(QK_SIZE / 128, M_ROWS / 128, 2);
        qkproj_kernel<<<grid, 256>>>((float*)px, head_q, head_k);
    }

    // 3) c = q k^T lower-triangle tiles into g_c
    qk_gemm_kernel<<<B_SIZE * 36, 256>>>();

    // 4) logits = x @ head_w^T via bf16 mma.sync 3-pass split
    {
        cudaFuncSetAttribute(mma_gemm_kernel, cudaFuncAttributeMaxDynamicSharedMemorySize, SMEM_DYN);
        dim3 grid(M_ROWS / BM, (V_SIZE + BN - 1) / BN);
        mma_gemm_kernel<<<grid, 256, SMEM_DYN>>>(
            (const __nv_bfloat16*)pxh, (const __nv_bfloat16*)pxl,
            (const __nv_bfloat16*)pwh, (const __nv_bfloat16*)pwl, logits);
    }

    // 5) causal copy-scatter from precomputed c (coalesced reads + atomics)
    scatter_kernel<<<M_ROWS, 256>>>(idx, logits);
}